// round 8
// baseline (speedup 1.0000x reference)
#include <cuda_runtime.h>

// Problem constants (DioLstm: B=4, NWORD=24, HID=512)
#define BD 4
#define NW 24
#define HD 512
#define H2 1024
#define H5 2560
#define KPAD 16

typedef unsigned long long u64;

// Chart state + per-cell projections (device globals; no allocs).
__device__ __align__(16) float g_chartH[BD*NW*NW*HD];
__device__ __align__(16) float g_chartC[BD*NW*NW*HD];
__device__ __align__(16) float g_chartS[BD*NW*NW];
__device__ __align__(16) float g_Ui[BD*NW*NW*H5];      // Wi @ h   per cell
__device__ __align__(16) float g_Us[BD*NW*NW*H5];      // Ws @ h   per cell
__device__ __align__(16) float g_aL[BD*NW*NW*H2];      // [h;c]^T @ Wbil per cell
__device__ __align__(16) float g_WiT[(HD+KPAD)*H5];    // Wi^T : [k][o], K-padded
__device__ __align__(16) float g_WsT[(HD+KPAD)*H5];
__device__ __align__(16) float g_Wb [(H2+KPAD)*H2];    // Wbil copy, K-padded
__device__ __align__(16) float g_bias[H5];             // bi + bs + ins_bias
__device__ __align__(16) float g_part[2048*6144];      // K-split partials (2048 slots)

__device__ __forceinline__ int cellIdx(int b, int left, int len) {
    return (b*NW + left)*NW + len;
}

__device__ __forceinline__ float sigf(float x) {
    return __fdividef(1.0f, 1.0f + __expf(-x));
}
__device__ __forceinline__ float tanhx(float x) {
    return __fdividef(2.0f, 1.0f + __expf(-2.0f*x)) - 1.0f;
}

// packed fp32x2 FMA: d = a*b + d   (SASS FFMA2; PTX-only form)
__device__ __forceinline__ void fma2(u64& d, u64 a, u64 b) {
    asm("fma.rn.f32x2 %0, %1, %2, %3;" : "=l"(d) : "l"(a), "l"(b), "l"(d));
}
__device__ __forceinline__ float2 u2f(u64 v) {
    float2 f;
    asm("mov.b64 {%0, %1}, %2;" : "=f"(f.x), "=f"(f.y) : "l"(v));
    return f;
}

// ---------------------------------------------------------------------------
// Launch #0: transpose Wi/Ws ([5H,H] -> [H,5H]) into padded arrays.
// ---------------------------------------------------------------------------
__global__ void transposeK(const float* __restrict__ Wi, const float* __restrict__ Ws) {
    __shared__ float tile[32][33];
    const float* src = blockIdx.z ? Ws : Wi;
    float* dst = blockIdx.z ? g_WsT : g_WiT;
    int r0 = blockIdx.y * 32;   // o dim (2560)
    int c0 = blockIdx.x * 32;   // k dim (512)
    #pragma unroll
    for (int i = threadIdx.y; i < 32; i += 8)
        tile[i][threadIdx.x] = src[(r0 + i)*HD + c0 + threadIdx.x];
    __syncthreads();
    #pragma unroll
    for (int i = threadIdx.y; i < 32; i += 8)
        dst[(c0 + i)*H5 + r0 + threadIdx.x] = tile[threadIdx.x][i];
}

// Launch #1: leaves + combined bias.
__global__ void initK(const float* __restrict__ seqt,
                      const float* __restrict__ bi,
                      const float* __restrict__ bs) {
    int idx = blockIdx.x*256 + threadIdx.x;
    if (idx < BD*NW*HD) {
        int i = idx % HD;
        int w = (idx / HD) % NW;
        int b = idx / (HD*NW);
        int c = cellIdx(b, w, 0);
        g_chartH[(size_t)c*HD + i] = seqt[(b*NW + w)*H2 + i];
        g_chartC[(size_t)c*HD + i] = seqt[(b*NW + w)*H2 + HD + i];
        if (i == 0) g_chartS[c] = 0.0f;
    }
    if (idx < H5) {
        float extra = (idx >= HD && idx < 3*HD) ? 1.0f : 0.0f;
        g_bias[idx] = bi[idx] + bs[idx] + extra;
    }
}

// Launch #2: copy Wbil into padded g_Wb.
__global__ void copyWbK(const float* __restrict__ Wbil) {
    int idx = blockIdx.x*256 + threadIdx.x;   // H2*H2 = 1M elements
    g_Wb[idx] = Wbil[idx];
}

// ---------------------------------------------------------------------------
// Per-cell projection GEMM, K-split, FFMA2 inner loop.
// Thread owns 4 output cols (two f32x2 lanes) x CT cells.
// Block: 128 threads -> 512 cols; col space 6144 = 12 tiles.
// grid (12, ceil(M/CT), S); this block reduces K rows [z*KS, (z+1)*KS).
// ---------------------------------------------------------------------------
template<int CT>
__global__ void __launch_bounds__(128) projK(int L, int P, int log2S) {
    const int colBase = blockIdx.x * 512;
    const int M = BD*P;
    const int cbase = blockIdx.y * CT;
    const int z = blockIdx.z;

    const float* W; int seg, ncols, logK;
    if (colBase < H5)        { W = g_WiT; seg = 0;    ncols = H5; logK = 9;  }
    else if (colBase < 2*H5) { W = g_WsT; seg = H5;   ncols = H5; logK = 9;  }
    else                     { W = g_Wb;  seg = 2*H5; ncols = H2; logK = 10; }
    const int logKS = logK - log2S;
    const int KS = 1 << logKS;               // >= 32, multiple of 8, <= 256
    const int kbeg = z << logKS;
    const bool bil = (logK == 10);

    // duplicated activations: xs2[c][i] = (x, x)
    __shared__ __align__(16) float2 xs2[CT][256];
    for (int t = threadIdx.x; t < (CT << logKS); t += 128) {
        int c = t >> logKS, i = t & (KS - 1);
        float v = 0.0f;
        int cell = cbase + c;
        if (cell < M) {
            int b = cell / P, left = cell - b*P;
            int ci = cellIdx(b, left, L);
            int g = kbeg + i;
            if (!bil) v = g_chartH[(size_t)ci*HD + g];
            else      v = (g < HD) ? g_chartH[(size_t)ci*HD + g]
                                   : g_chartC[(size_t)ci*HD + (g - HD)];
        }
        xs2[c][i] = make_float2(v, v);
    }
    __syncthreads();

    const int wcol = (colBase - seg) + 4*threadIdx.x;
    const char* wbase = (const char*)(W + (size_t)kbeg * ncols + wcol);
    const size_t wstride = (size_t)ncols * 4;   // bytes per K row

    u64 aLo[CT], aHi[CT];
    #pragma unroll
    for (int c = 0; c < CT; c++) { aLo[c] = 0ull; aHi[c] = 0ull; }

    ulonglong2 wA[4], wB[4];
    #pragma unroll
    for (int j = 0; j < 4; j++)
        wA[j] = *(const ulonglong2*)(wbase + (size_t)j * wstride);

    for (int k = 0; k < KS; k += 8) {
        #pragma unroll
        for (int j = 0; j < 4; j++)
            wB[j] = *(const ulonglong2*)(wbase + (size_t)(k + 4 + j) * wstride);

        #pragma unroll
        for (int c = 0; c < CT; c++) {
            ulonglong2 x01 = *(const ulonglong2*)&xs2[c][k];
            ulonglong2 x23 = *(const ulonglong2*)&xs2[c][k + 2];
            fma2(aLo[c], wA[0].x, x01.x);  fma2(aHi[c], wA[0].y, x01.x);
            fma2(aLo[c], wA[1].x, x01.y);  fma2(aHi[c], wA[1].y, x01.y);
            fma2(aLo[c], wA[2].x, x23.x);  fma2(aHi[c], wA[2].y, x23.x);
            fma2(aLo[c], wA[3].x, x23.y);  fma2(aHi[c], wA[3].y, x23.y);
        }

        #pragma unroll
        for (int j = 0; j < 4; j++)
            wA[j] = *(const ulonglong2*)(wbase + (size_t)(k + 8 + j) * wstride);

        #pragma unroll
        for (int c = 0; c < CT; c++) {
            ulonglong2 x01 = *(const ulonglong2*)&xs2[c][k + 4];
            ulonglong2 x23 = *(const ulonglong2*)&xs2[c][k + 6];
            fma2(aLo[c], wB[0].x, x01.x);  fma2(aHi[c], wB[0].y, x01.x);
            fma2(aLo[c], wB[1].x, x01.y);  fma2(aHi[c], wB[1].y, x01.y);
            fma2(aLo[c], wB[2].x, x23.x);  fma2(aHi[c], wB[2].y, x23.x);
            fma2(aLo[c], wB[3].x, x23.y);  fma2(aHi[c], wB[3].y, x23.y);
        }
    }

    // write partials: slot = z * (gridDim.y*CT) + cell
    const int slotStride = gridDim.y * CT;
    float* pp = g_part + ((size_t)(z * slotStride + cbase)) * 6144
                       + colBase + 4*threadIdx.x;
    #pragma unroll
    for (int c = 0; c < CT; c++) {
        if (cbase + c < M) {
            float2 lo = u2f(aLo[c]), hi = u2f(aHi[c]);
            *(float4*)(pp + (size_t)c * 6144) = make_float4(lo.x, lo.y, hi.x, hi.y);
        }
    }
}

// ---------------------------------------------------------------------------
// Sum the S K-split partials into g_Ui / g_Us / g_aL (float4 wide).
// ---------------------------------------------------------------------------
__global__ void reduceK(int L, int P, int slotStride, int S) {
    int idx = blockIdx.x*256 + threadIdx.x;
    int M = BD*P;
    if (idx >= M*1536) return;                  // 1536 float4 per cell
    int cell = idx / 1536, c4 = idx - cell*1536;
    int col = c4 * 4;
    float4 s = make_float4(0.f, 0.f, 0.f, 0.f);
    for (int z = 0; z < S; z++) {
        const float4 v = *(const float4*)&g_part[((size_t)(z*slotStride + cell))*6144 + col];
        s.x += v.x; s.y += v.y; s.z += v.z; s.w += v.w;
    }
    int b = cell / P, left = cell - b*P;
    int ci = cellIdx(b, left, L);
    if (col < H5)        *(float4*)&g_Ui[(size_t)ci*H5 + col]          = s;
    else if (col < 2*H5) *(float4*)&g_Us[(size_t)ci*H5 + (col - H5)]   = s;
    else                 *(float4*)&g_aL[(size_t)ci*H2 + (col - 2*H5)] = s;
}

// ---------------------------------------------------------------------------
// Pairs kernel: compat + softmax + gated combine.
// grid = BD*P*SPLIT blocks of (HD/SPLIT) threads; block owns span + e-chunk.
// ---------------------------------------------------------------------------
__global__ void pairsK(int L, int SPLIT, float* __restrict__ out) {
    const int P = NW - L;
    const int npair = BD*P;
    const int pairId = blockIdx.x % npair;
    const int s = blockIdx.x / npair;
    const int b = pairId / P, left = pairId - b*P;
    const int chunk = blockDim.x;
    const int e0 = s * chunk;

    __shared__ float s_w[24];
    __shared__ float s_comp[24];
    __shared__ int   s_offL[24], s_offR[24];

    const int tid = threadIdx.x, warp = tid >> 5, lane = tid & 31;
    const int nw = blockDim.x >> 5;

    // pass 1: compat_k = aL(left,k) . [rH;rC] + lS + rS
    for (int k = warp; k < L; k += nw) {
        int r = left + k + 1, rl = L - 1 - k;
        int cl = cellIdx(b, left, k), cr = cellIdx(b, r, rl);
        const float* a  = g_aL     + (size_t)cl*H2;
        const float* rh = g_chartH + (size_t)cr*HD;
        const float* rc = g_chartC + (size_t)cr*HD;
        float acc = 0.0f;
        for (int i = lane; i < HD; i += 32)
            acc = fmaf(a[i], rh[i], fmaf(a[HD + i], rc[i], acc));
        #pragma unroll
        for (int off = 16; off; off >>= 1)
            acc += __shfl_down_sync(0xffffffffu, acc, off);
        if (lane == 0) {
            s_comp[k] = acc + g_chartS[cl] + g_chartS[cr];
            s_offL[k] = cl; s_offR[k] = cr;
        }
    }
    __syncthreads();

    // softmax over k (warp 0)
    if (warp == 0) {
        float c = (lane < L) ? s_comp[lane] : -3.402823466e38f;
        float m = c;
        #pragma unroll
        for (int off = 16; off; off >>= 1)
            m = fmaxf(m, __shfl_xor_sync(0xffffffffu, m, off));
        float e = (lane < L) ? __expf(c - m) : 0.0f;
        float ssum = e;
        #pragma unroll
        for (int off = 16; off; off >>= 1)
            ssum += __shfl_xor_sync(0xffffffffu, ssum, off);
        float w = __fdividef(e, ssum);
        if (lane < L) s_w[lane] = w;
        float sn = (lane < L) ? w * c : 0.0f;
        #pragma unroll
        for (int off = 16; off; off >>= 1)
            sn += __shfl_xor_sync(0xffffffffu, sn, off);
        if (lane == 0 && s == 0) g_chartS[cellIdx(b, left, L)] = sn;
    }
    __syncthreads();

    // pass 2: gates + weighted combine for this block's e-chunk
    {
        int e = e0 + tid;
        float b0 = g_bias[e],        b1 = g_bias[HD + e],  b2 = g_bias[2*HD + e];
        float b3 = g_bias[3*HD + e], b4 = g_bias[4*HD + e];
        float ah = 0.0f, ac = 0.0f;
        for (int k = 0; k < L; k++) {
            int cl = s_offL[k], cr = s_offR[k];
            const float* ui = g_Ui + (size_t)cl*H5;
            const float* us = g_Us + (size_t)cr*H5;
            float p0 = ui[e]        + us[e]        + b0;
            float p1 = ui[HD + e]   + us[HD + e]   + b1;
            float p2 = ui[2*HD + e] + us[2*HD + e] + b2;
            float p3 = ui[3*HD + e] + us[3*HD + e] + b3;
            float p4 = ui[4*HD + e] + us[4*HD + e] + b4;
            float lc = g_chartC[(size_t)cl*HD + e];
            float rc = g_chartC[(size_t)cr*HD + e];
            float ig = sigf(p0), lf = sigf(p1), rf = sigf(p2), og = sigf(p4);
            float gg = tanhx(p3);
            float mem = fmaf(lf, lc, fmaf(rf, rc, ig * gg));
            float hh = og * tanhx(mem);
            float w = s_w[k];
            ah = fmaf(w, hh, ah);
            ac = fmaf(w, mem, ac);
        }
        int cn = cellIdx(b, left, L);
        g_chartH[(size_t)cn*HD + e] = ah;
        g_chartC[(size_t)cn*HD + e] = ac;
        if (out) {
            out[b*H2 + e]      = ah;
            out[b*H2 + HD + e] = ac;
        }
    }
}

// ---------------------------------------------------------------------------
// Host side
// ---------------------------------------------------------------------------
static void launchProj(int L, int P) {
    int M = BD * P;
    int CT = (M >= 32) ? 8 : (M >= 16) ? 4 : 2;
    int tiles = (M + CT - 1) / CT;
    int S = 1, l2s = 0;
    // grow S for warp supply; KS >= 32 needs S <= 16; scratch <= 2048 slots
    while (12 * tiles * S < 1200 && S < 16 && 2 * S * tiles * CT <= 2048) {
        S <<= 1; l2s++;
    }
    if (CT == 8)      projK<8><<<dim3(12, tiles, S), 128>>>(L, P, l2s);
    else if (CT == 4) projK<4><<<dim3(12, tiles, S), 128>>>(L, P, l2s);
    else              projK<2><<<dim3(12, tiles, S), 128>>>(L, P, l2s);
    reduceK<<<(M*1536 + 255)/256, 256>>>(L, P, tiles*CT, S);
}

static int pickSplit(int P) {
    int np = BD * P;
    if (np >= 64) return 4;   // chunk 128
    return 8;                 // chunk 64
}

extern "C" void kernel_launch(void* const* d_in, const int* in_sizes, int n_in,
                              void* d_out, int out_size) {
    const float* seqt = (const float*)d_in[0];
    const float* Wi   = (const float*)d_in[1];
    const float* bi   = (const float*)d_in[2];
    const float* Ws   = (const float*)d_in[3];
    const float* bs   = (const float*)d_in[4];
    const float* Wbil = (const float*)d_in[5];
    float* out = (float*)d_out;

    // Exactly 3 setup launches => ncu capture (launch #3) = projK(L=0)
    transposeK<<<dim3(16, 80, 2), dim3(32, 8)>>>(Wi, Ws);   // #0
    initK<<<192, 256>>>(seqt, bi, bs);                      // #1
    copyWbK<<<(H2*H2)/256, 256>>>(Wbil);                    // #2

    launchProj(0, NW);                                      // #3 + #4

    for (int L = 1; L < NW; L++) {
        int P = NW - L;
        int SPLIT = pickSplit(P);
        pairsK<<<BD*P*SPLIT, HD/SPLIT>>>(L, SPLIT, (L == NW - 1) ? out : nullptr);
        if (L < NW - 1) launchProj(L, P);
    }
}

// round 9
// speedup vs baseline: 1.3726x; 1.3726x over previous
#include <cuda_runtime.h>

// Problem constants (DioLstm: B=4, NWORD=24, HID=512)
#define BD 4
#define NW 24
#define HD 512
#define H2 1024
#define H5 2560
#define KPAD 16

typedef unsigned long long u64;

// Chart state + per-cell projections (device globals; no allocs).
__device__ __align__(16) float g_chartH[BD*NW*NW*HD];
__device__ __align__(16) float g_chartC[BD*NW*NW*HD];
__device__ __align__(16) float g_chartS[BD*NW*NW];
__device__ __align__(16) float g_Ui[BD*NW*NW*H5];      // Wi @ h   per cell
__device__ __align__(16) float g_Us[BD*NW*NW*H5];      // Ws @ h   per cell
__device__ __align__(16) float g_aL[BD*NW*NW*H2];      // [h;c]^T @ Wbil per cell
__device__ __align__(16) float g_WiT[(HD+KPAD)*H5];    // Wi^T : [k][o], K-padded
__device__ __align__(16) float g_WsT[(HD+KPAD)*H5];
__device__ __align__(16) float g_Wb [(H2+KPAD)*H2];    // Wbil copy, K-padded
__device__ __align__(16) float g_bias[H5];             // bi + bs + ins_bias
__device__ __align__(16) float g_part[2048*6144];      // K-split partials
__device__ int g_cnt[256];                             // per-tile arrival counters (zero-init; self-resetting)

__device__ __forceinline__ int cellIdx(int b, int left, int len) {
    return (b*NW + left)*NW + len;
}

__device__ __forceinline__ float sigf(float x) {
    return __fdividef(1.0f, 1.0f + __expf(-x));
}
__device__ __forceinline__ float tanhx(float x) {
    return __fdividef(2.0f, 1.0f + __expf(-2.0f*x)) - 1.0f;
}

// packed fp32x2 FMA: d = a*b + d   (SASS FFMA2; PTX-only form)
__device__ __forceinline__ void fma2(u64& d, u64 a, u64 b) {
    asm("fma.rn.f32x2 %0, %1, %2, %3;" : "=l"(d) : "l"(a), "l"(b), "l"(d));
}
__device__ __forceinline__ float2 u2f(u64 v) {
    float2 f;
    asm("mov.b64 {%0, %1}, %2;" : "=f"(f.x), "=f"(f.y) : "l"(v));
    return f;
}

// ---------------------------------------------------------------------------
// Launch #0: transpose Wi/Ws ([5H,H] -> [H,5H]) into padded arrays.
// ---------------------------------------------------------------------------
__global__ void transposeK(const float* __restrict__ Wi, const float* __restrict__ Ws) {
    __shared__ float tile[32][33];
    const float* src = blockIdx.z ? Ws : Wi;
    float* dst = blockIdx.z ? g_WsT : g_WiT;
    int r0 = blockIdx.y * 32;   // o dim (2560)
    int c0 = blockIdx.x * 32;   // k dim (512)
    #pragma unroll
    for (int i = threadIdx.y; i < 32; i += 8)
        tile[i][threadIdx.x] = src[(r0 + i)*HD + c0 + threadIdx.x];
    __syncthreads();
    #pragma unroll
    for (int i = threadIdx.y; i < 32; i += 8)
        dst[(c0 + i)*H5 + r0 + threadIdx.x] = tile[threadIdx.x][i];
}

// Launch #1: leaves + combined bias.
__global__ void initK(const float* __restrict__ seqt,
                      const float* __restrict__ bi,
                      const float* __restrict__ bs) {
    int idx = blockIdx.x*256 + threadIdx.x;
    if (idx < BD*NW*HD) {
        int i = idx % HD;
        int w = (idx / HD) % NW;
        int b = idx / (HD*NW);
        int c = cellIdx(b, w, 0);
        g_chartH[(size_t)c*HD + i] = seqt[(b*NW + w)*H2 + i];
        g_chartC[(size_t)c*HD + i] = seqt[(b*NW + w)*H2 + HD + i];
        if (i == 0) g_chartS[c] = 0.0f;
    }
    if (idx < H5) {
        float extra = (idx >= HD && idx < 3*HD) ? 1.0f : 0.0f;
        g_bias[idx] = bi[idx] + bs[idx] + extra;
    }
}

// Launch #2: copy Wbil into padded g_Wb.
__global__ void copyWbK(const float* __restrict__ Wbil) {
    int idx = blockIdx.x*256 + threadIdx.x;   // H2*H2 = 1M elements
    g_Wb[idx] = Wbil[idx];
}

// ---------------------------------------------------------------------------
// Per-cell projection GEMM, K-split, FFMA2 inner loop, FUSED reduction:
// the last-arriving z-block of each (colTile, cellTile) sums the S partials
// (fixed z order -> deterministic) and writes Ui/Us/aL, then resets the
// counter so the next launch/replay starts from zero.
// Thread owns 4 output cols (two f32x2 lanes) x CT cells. 128 thr = 512 cols.
// grid (12, ceil(M/CT), S); block reduces K rows [z*KS, (z+1)*KS).
// ---------------------------------------------------------------------------
template<int CT>
__global__ void __launch_bounds__(128) projK(int L, int P, int log2S) {
    const int colBase = blockIdx.x * 512;
    const int M = BD*P;
    const int cbase = blockIdx.y * CT;
    const int z = blockIdx.z;
    const int S = gridDim.z;

    const float* W; int seg, ncols, logK;
    if (colBase < H5)        { W = g_WiT; seg = 0;    ncols = H5; logK = 9;  }
    else if (colBase < 2*H5) { W = g_WsT; seg = H5;   ncols = H5; logK = 9;  }
    else                     { W = g_Wb;  seg = 2*H5; ncols = H2; logK = 10; }
    const int logKS = logK - log2S;
    const int KS = 1 << logKS;               // >= 32, multiple of 8, <= 256
    const int kbeg = z << logKS;
    const bool bil = (logK == 10);

    // duplicated activations: xs2[c][i] = (x, x)
    __shared__ __align__(16) float2 xs2[CT][256];
    for (int t = threadIdx.x; t < (CT << logKS); t += 128) {
        int c = t >> logKS, i = t & (KS - 1);
        float v = 0.0f;
        int cell = cbase + c;
        if (cell < M) {
            int b = cell / P, left = cell - b*P;
            int ci = cellIdx(b, left, L);
            int g = kbeg + i;
            if (!bil) v = g_chartH[(size_t)ci*HD + g];
            else      v = (g < HD) ? g_chartH[(size_t)ci*HD + g]
                                   : g_chartC[(size_t)ci*HD + (g - HD)];
        }
        xs2[c][i] = make_float2(v, v);
    }
    __syncthreads();

    const int wcol = (colBase - seg) + 4*threadIdx.x;
    const char* wbase = (const char*)(W + (size_t)kbeg * ncols + wcol);
    const size_t wstride = (size_t)ncols * 4;   // bytes per K row

    u64 aLo[CT], aHi[CT];
    #pragma unroll
    for (int c = 0; c < CT; c++) { aLo[c] = 0ull; aHi[c] = 0ull; }

    ulonglong2 wA[4], wB[4];
    #pragma unroll
    for (int j = 0; j < 4; j++)
        wA[j] = *(const ulonglong2*)(wbase + (size_t)j * wstride);

    for (int k = 0; k < KS; k += 8) {
        #pragma unroll
        for (int j = 0; j < 4; j++)
            wB[j] = *(const ulonglong2*)(wbase + (size_t)(k + 4 + j) * wstride);

        #pragma unroll
        for (int c = 0; c < CT; c++) {
            ulonglong2 x01 = *(const ulonglong2*)&xs2[c][k];
            ulonglong2 x23 = *(const ulonglong2*)&xs2[c][k + 2];
            fma2(aLo[c], wA[0].x, x01.x);  fma2(aHi[c], wA[0].y, x01.x);
            fma2(aLo[c], wA[1].x, x01.y);  fma2(aHi[c], wA[1].y, x01.y);
            fma2(aLo[c], wA[2].x, x23.x);  fma2(aHi[c], wA[2].y, x23.x);
            fma2(aLo[c], wA[3].x, x23.y);  fma2(aHi[c], wA[3].y, x23.y);
        }

        #pragma unroll
        for (int j = 0; j < 4; j++)
            wA[j] = *(const ulonglong2*)(wbase + (size_t)(k + 8 + j) * wstride);

        #pragma unroll
        for (int c = 0; c < CT; c++) {
            ulonglong2 x01 = *(const ulonglong2*)&xs2[c][k + 4];
            ulonglong2 x23 = *(const ulonglong2*)&xs2[c][k + 6];
            fma2(aLo[c], wB[0].x, x01.x);  fma2(aHi[c], wB[0].y, x01.x);
            fma2(aLo[c], wB[1].x, x01.y);  fma2(aHi[c], wB[1].y, x01.y);
            fma2(aLo[c], wB[2].x, x23.x);  fma2(aHi[c], wB[2].y, x23.x);
            fma2(aLo[c], wB[3].x, x23.y);  fma2(aHi[c], wB[3].y, x23.y);
        }
    }

    // write partials: slot = z * (gridDim.y*CT) + cell
    const int slotStride = gridDim.y * CT;
    float* pp = g_part + ((size_t)(z * slotStride + cbase)) * 6144
                       + colBase + 4*threadIdx.x;
    #pragma unroll
    for (int c = 0; c < CT; c++) {
        if (cbase + c < M) {
            float2 lo = u2f(aLo[c]), hi = u2f(aHi[c]);
            *(float4*)(pp + (size_t)c * 6144) = make_float4(lo.x, lo.y, hi.x, hi.y);
        }
    }

    // ---- last-block-sums fused reduction (threadFenceReduction pattern) ----
    __threadfence();
    __shared__ int s_last;
    __syncthreads();
    if (threadIdx.x == 0) {
        int tileId = blockIdx.x * gridDim.y + blockIdx.y;
        int old = atomicAdd(&g_cnt[tileId], 1);
        s_last = (old == S - 1);
        if (s_last) g_cnt[tileId] = 0;    // self-reset for next launch/replay
    }
    __syncthreads();
    if (!s_last) return;

    float* dst; size_t stride;
    if (seg == 0)       { dst = g_Ui; stride = H5; }
    else if (seg == H5) { dst = g_Us; stride = H5; }
    else                { dst = g_aL; stride = H2; }

    const float* basep = g_part + (size_t)(colBase + 4*threadIdx.x);
    #pragma unroll
    for (int c = 0; c < CT; c++) {
        int cell = cbase + c;
        if (cell < M) {
            float4 s4 = make_float4(0.f, 0.f, 0.f, 0.f);
            for (int zz = 0; zz < S; zz++) {
                const float4 v = *(const float4*)(basep + ((size_t)(zz*slotStride + cell))*6144);
                s4.x += v.x; s4.y += v.y; s4.z += v.z; s4.w += v.w;
            }
            int b = cell / P, left = cell - b*P;
            int ci = cellIdx(b, left, L);
            *(float4*)(dst + (size_t)ci*stride + wcol) = s4;
        }
    }
}

// ---------------------------------------------------------------------------
// Pairs kernel: compat + softmax + gated combine.
// grid = BD*P*SPLIT blocks of (HD/SPLIT) threads; block owns span + e-chunk.
// ---------------------------------------------------------------------------
__global__ void pairsK(int L, int SPLIT, float* __restrict__ out) {
    const int P = NW - L;
    const int npair = BD*P;
    const int pairId = blockIdx.x % npair;
    const int s = blockIdx.x / npair;
    const int b = pairId / P, left = pairId - b*P;
    const int chunk = blockDim.x;
    const int e0 = s * chunk;

    __shared__ float s_w[24];
    __shared__ float s_comp[24];
    __shared__ int   s_offL[24], s_offR[24];

    const int tid = threadIdx.x, warp = tid >> 5, lane = tid & 31;
    const int nw = blockDim.x >> 5;

    // pass 1: compat_k = aL(left,k) . [rH;rC] + lS + rS
    for (int k = warp; k < L; k += nw) {
        int r = left + k + 1, rl = L - 1 - k;
        int cl = cellIdx(b, left, k), cr = cellIdx(b, r, rl);
        const float* a  = g_aL     + (size_t)cl*H2;
        const float* rh = g_chartH + (size_t)cr*HD;
        const float* rc = g_chartC + (size_t)cr*HD;
        float acc = 0.0f;
        for (int i = lane; i < HD; i += 32)
            acc = fmaf(a[i], rh[i], fmaf(a[HD + i], rc[i], acc));
        #pragma unroll
        for (int off = 16; off; off >>= 1)
            acc += __shfl_down_sync(0xffffffffu, acc, off);
        if (lane == 0) {
            s_comp[k] = acc + g_chartS[cl] + g_chartS[cr];
            s_offL[k] = cl; s_offR[k] = cr;
        }
    }
    __syncthreads();

    // softmax over k (warp 0)
    if (warp == 0) {
        float c = (lane < L) ? s_comp[lane] : -3.402823466e38f;
        float m = c;
        #pragma unroll
        for (int off = 16; off; off >>= 1)
            m = fmaxf(m, __shfl_xor_sync(0xffffffffu, m, off));
        float e = (lane < L) ? __expf(c - m) : 0.0f;
        float ssum = e;
        #pragma unroll
        for (int off = 16; off; off >>= 1)
            ssum += __shfl_xor_sync(0xffffffffu, ssum, off);
        float w = __fdividef(e, ssum);
        if (lane < L) s_w[lane] = w;
        float sn = (lane < L) ? w * c : 0.0f;
        #pragma unroll
        for (int off = 16; off; off >>= 1)
            sn += __shfl_xor_sync(0xffffffffu, sn, off);
        if (lane == 0 && s == 0) g_chartS[cellIdx(b, left, L)] = sn;
    }
    __syncthreads();

    // pass 2: gates + weighted combine for this block's e-chunk
    {
        int e = e0 + tid;
        float b0 = g_bias[e],        b1 = g_bias[HD + e],  b2 = g_bias[2*HD + e];
        float b3 = g_bias[3*HD + e], b4 = g_bias[4*HD + e];
        float ah = 0.0f, ac = 0.0f;
        for (int k = 0; k < L; k++) {
            int cl = s_offL[k], cr = s_offR[k];
            const float* ui = g_Ui + (size_t)cl*H5;
            const float* us = g_Us + (size_t)cr*H5;
            float p0 = ui[e]        + us[e]        + b0;
            float p1 = ui[HD + e]   + us[HD + e]   + b1;
            float p2 = ui[2*HD + e] + us[2*HD + e] + b2;
            float p3 = ui[3*HD + e] + us[3*HD + e] + b3;
            float p4 = ui[4*HD + e] + us[4*HD + e] + b4;
            float lc = g_chartC[(size_t)cl*HD + e];
            float rc = g_chartC[(size_t)cr*HD + e];
            float ig = sigf(p0), lf = sigf(p1), rf = sigf(p2), og = sigf(p4);
            float gg = tanhx(p3);
            float mem = fmaf(lf, lc, fmaf(rf, rc, ig * gg));
            float hh = og * tanhx(mem);
            float w = s_w[k];
            ah = fmaf(w, hh, ah);
            ac = fmaf(w, mem, ac);
        }
        int cn = cellIdx(b, left, L);
        g_chartH[(size_t)cn*HD + e] = ah;
        g_chartC[(size_t)cn*HD + e] = ac;
        if (out) {
            out[b*H2 + e]      = ah;
            out[b*H2 + HD + e] = ac;
        }
    }
}

// ---------------------------------------------------------------------------
// Host side
// ---------------------------------------------------------------------------
static void launchProj(int L, int P) {
    int M = BD * P;
    int CT = (M >= 64) ? 8 : (M >= 24) ? 4 : 2;          // R7 thresholds
    int tiles = (M + CT - 1) / CT;
    int target   = (M >= 80) ? 1200 : 512;               // aggressive S only for big M
    int maxSlots = (M >= 80) ? 2048 : 1024;
    int S = 1, l2s = 0;
    while (12 * tiles * S < target && S < 16 && 2 * S * tiles * CT <= maxSlots) {
        S <<= 1; l2s++;
    }
    if (CT == 8)      projK<8><<<dim3(12, tiles, S), 128>>>(L, P, l2s);
    else if (CT == 4) projK<4><<<dim3(12, tiles, S), 128>>>(L, P, l2s);
    else              projK<2><<<dim3(12, tiles, S), 128>>>(L, P, l2s);
}

static int pickSplit(int P) {
    int np = BD * P;
    if (np >= 64) return 4;   // chunk 128
    return 8;                 // chunk 64
}

extern "C" void kernel_launch(void* const* d_in, const int* in_sizes, int n_in,
                              void* d_out, int out_size) {
    const float* seqt = (const float*)d_in[0];
    const float* Wi   = (const float*)d_in[1];
    const float* bi   = (const float*)d_in[2];
    const float* Ws   = (const float*)d_in[3];
    const float* bs   = (const float*)d_in[4];
    const float* Wbil = (const float*)d_in[5];
    float* out = (float*)d_out;

    // Exactly 3 setup launches => ncu capture (launch #3) = projK(L=0)
    transposeK<<<dim3(16, 80, 2), dim3(32, 8)>>>(Wi, Ws);   // #0
    initK<<<192, 256>>>(seqt, bi, bs);                      // #1
    copyWbK<<<(H2*H2)/256, 256>>>(Wbil);                    // #2

    launchProj(0, NW);                                      // #3  (M = 96)

    for (int L = 1; L < NW; L++) {
        int P = NW - L;
        int SPLIT = pickSplit(P);
        pairsK<<<BD*P*SPLIT, HD/SPLIT>>>(L, SPLIT, (L == NW - 1) ? out : nullptr);
        if (L < NW - 1) launchProj(L, P);
    }
}